// round 9
// baseline (speedup 1.0000x reference)
#include <cuda_runtime.h>

// Problem constants (fixed shapes)
#define T_TOK 8192
#define D_IN  1024
#define H1    128
#define QDIM  32
#define HALFD 8
#define KNN   8
#define NKEYS 256

// GEMM tiling
#define BM 64
#define BN 128
#define BK 16
#define NKT (D_IN / BK)

// Scratch (device globals: allocation-free rule)
__device__ __align__(16) float g_h[T_TOK * H1];     // 4 MB
__device__ __align__(16) float g_q[T_TOK * QDIM];   // 1 MB
__device__ float g_wt[T_TOK * 16];                  // 512 KB
__device__ int   g_id[T_TOK * 16];                  // 512 KB

// Packed dual-fp32 FMA (B300 FFMA2 path; 2x FFMA issue throughput)
#define FMA2(d, a, b) asm("fma.rn.f32x2 %0, %1, %2, %0;" : "+l"(d) : "l"(a), "l"(b))

// ---------------------------------------------------------------------------
// Kernel 1: h = relu(x @ W1^T + b1)   [8192 x 1024] @ [1024 x 128] -> [8192 x 128]
// fp32, f32x2-packed over the token dimension (pairs of tokens per accumulator).
// Block: 64 tokens x 128 outputs, BK=16, 128 threads, thread tile 8x8.
// ---------------------------------------------------------------------------
__global__ __launch_bounds__(128, 1)
void k1_gemm_relu(const float* __restrict__ x, const float* __restrict__ W1,
                  const float* __restrict__ b1)
{
    __shared__ __align__(16) float  Xs[2][BK * BM];   // k-major, tokens contiguous
    __shared__ __align__(16) float2 Ws[2][BK * BN];   // k-major, (w,w) duplicated pairs

    const int tid = threadIdx.x;
    const int tx  = tid & 15;   // output-column group (0..15)
    const int ty  = tid >> 4;   // token-pair group   (0..7)
    const int t0  = blockIdx.x * BM;

    const int lt = tid >> 2;        // loader row   0..31
    const int lk = (tid & 3) << 2;  // loader k sub 0,4,8,12

    unsigned long long acc[4][8];
#pragma unroll
    for (int i = 0; i < 4; i++)
#pragma unroll
        for (int j = 0; j < 8; j++) acc[i][j] = 0ull;

    const float* xrow0 = x  + (size_t)(t0 + lt) * D_IN + lk;
    const float* xrow1 = x  + (size_t)(t0 + lt + 32) * D_IN + lk;
    const float* wrow0 = W1 + (size_t)lt * D_IN + lk;

    float4 px0, px1, pw0, pw1, pw2, pw3;

    // Prefetch tile 0
    px0 = *(const float4*)(xrow0);
    px1 = *(const float4*)(xrow1);
    pw0 = *(const float4*)(wrow0);
    pw1 = *(const float4*)(wrow0 + 32 * D_IN);
    pw2 = *(const float4*)(wrow0 + 64 * D_IN);
    pw3 = *(const float4*)(wrow0 + 96 * D_IN);

#define STORE_TILE(buf)                                                        \
    do {                                                                       \
        Xs[buf][(lk + 0) * BM + lt]      = px0.x;                              \
        Xs[buf][(lk + 1) * BM + lt]      = px0.y;                              \
        Xs[buf][(lk + 2) * BM + lt]      = px0.z;                              \
        Xs[buf][(lk + 3) * BM + lt]      = px0.w;                              \
        Xs[buf][(lk + 0) * BM + lt + 32] = px1.x;                              \
        Xs[buf][(lk + 1) * BM + lt + 32] = px1.y;                              \
        Xs[buf][(lk + 2) * BM + lt + 32] = px1.z;                              \
        Xs[buf][(lk + 3) * BM + lt + 32] = px1.w;                              \
        Ws[buf][(lk + 0) * BN + lt]      = make_float2(pw0.x, pw0.x);          \
        Ws[buf][(lk + 1) * BN + lt]      = make_float2(pw0.y, pw0.y);          \
        Ws[buf][(lk + 2) * BN + lt]      = make_float2(pw0.z, pw0.z);          \
        Ws[buf][(lk + 3) * BN + lt]      = make_float2(pw0.w, pw0.w);          \
        Ws[buf][(lk + 0) * BN + lt + 32] = make_float2(pw1.x, pw1.x);          \
        Ws[buf][(lk + 1) * BN + lt + 32] = make_float2(pw1.y, pw1.y);          \
        Ws[buf][(lk + 2) * BN + lt + 32] = make_float2(pw1.z, pw1.z);          \
        Ws[buf][(lk + 3) * BN + lt + 32] = make_float2(pw1.w, pw1.w);          \
        Ws[buf][(lk + 0) * BN + lt + 64] = make_float2(pw2.x, pw2.x);          \
        Ws[buf][(lk + 1) * BN + lt + 64] = make_float2(pw2.y, pw2.y);          \
        Ws[buf][(lk + 2) * BN + lt + 64] = make_float2(pw2.z, pw2.z);          \
        Ws[buf][(lk + 3) * BN + lt + 64] = make_float2(pw2.w, pw2.w);          \
        Ws[buf][(lk + 0) * BN + lt + 96] = make_float2(pw3.x, pw3.x);          \
        Ws[buf][(lk + 1) * BN + lt + 96] = make_float2(pw3.y, pw3.y);          \
        Ws[buf][(lk + 2) * BN + lt + 96] = make_float2(pw3.z, pw3.z);          \
        Ws[buf][(lk + 3) * BN + lt + 96] = make_float2(pw3.w, pw3.w);          \
    } while (0)

    STORE_TILE(0);
    __syncthreads();

#pragma unroll 1
    for (int kt = 0; kt < NKT; kt++) {
        const int cur = kt & 1;
        if (kt < NKT - 1) {
            const int k0 = (kt + 1) * BK;
            px0 = *(const float4*)(xrow0 + k0);
            px1 = *(const float4*)(xrow1 + k0);
            pw0 = *(const float4*)(wrow0 + k0);
            pw1 = *(const float4*)(wrow0 + 32 * D_IN + k0);
            pw2 = *(const float4*)(wrow0 + 64 * D_IN + k0);
            pw3 = *(const float4*)(wrow0 + 96 * D_IN + k0);
        }
#pragma unroll
        for (int k = 0; k < BK; k++) {
            const unsigned long long a0 =
                *(const unsigned long long*)&Xs[cur][k * BM + (ty << 1)];
            const unsigned long long a1 =
                *(const unsigned long long*)&Xs[cur][k * BM + ((ty + 8) << 1)];
            const unsigned long long a2 =
                *(const unsigned long long*)&Xs[cur][k * BM + ((ty + 16) << 1)];
            const unsigned long long a3 =
                *(const unsigned long long*)&Xs[cur][k * BM + ((ty + 24) << 1)];
#pragma unroll
            for (int jj = 0; jj < 8; jj++) {
                const unsigned long long bb =
                    *(const unsigned long long*)&Ws[cur][k * BN + jj * 16 + tx];
                FMA2(acc[0][jj], a0, bb);
                FMA2(acc[1][jj], a1, bb);
                FMA2(acc[2][jj], a2, bb);
                FMA2(acc[3][jj], a3, bb);
            }
        }
        if (kt < NKT - 1) STORE_TILE(cur ^ 1);
        __syncthreads();
    }

    // Epilogue: bias + relu, unpack token pairs
#pragma unroll
    for (int jj = 0; jj < 8; jj++) {
        const int j = jj * 16 + tx;
        const float bias = b1[j];
#pragma unroll
        for (int ii = 0; ii < 4; ii++) {
            const int r0 = t0 + ((ii * 8 + ty) << 1);
            const unsigned long long v = acc[ii][jj];
            const float lo = __uint_as_float((unsigned)(v & 0xffffffffull)) + bias;
            const float hi = __uint_as_float((unsigned)(v >> 32)) + bias;
            g_h[(size_t)r0 * H1 + j]       = fmaxf(lo, 0.0f);
            g_h[(size_t)(r0 + 1) * H1 + j] = fmaxf(hi, 0.0f);
        }
    }
}

// ---------------------------------------------------------------------------
// Kernel 2: q = h @ W2^T + b2   ([8192 x 128] @ [128 x 32]) -> g_q
// Warp per token; lane c computes q[c]. W2 transposed in smem (conflict-free).
// ---------------------------------------------------------------------------
__global__ __launch_bounds__(256, 1)
void k2_q(const float* __restrict__ W2, const float* __restrict__ b2)
{
    __shared__ float W2T[H1 * QDIM];  // [j][c]
    __shared__ float hs[8][H1];

    const int tid  = threadIdx.x;
    const int w    = tid >> 5;
    const int lane = tid & 31;

    for (int i = tid; i < H1 * QDIM; i += 256)
        W2T[(i & (H1 - 1)) * QDIM + (i >> 7)] = W2[i];   // i = c*128 + j
    const float bias = b2[lane];
    __syncthreads();

    for (int g = blockIdx.x; g < T_TOK / 8; g += gridDim.x) {
        const int t = g * 8 + w;
        const float4 hv = *(const float4*)(g_h + (size_t)t * H1 + (lane << 2));
        hs[w][(lane << 2) + 0] = hv.x;
        hs[w][(lane << 2) + 1] = hv.y;
        hs[w][(lane << 2) + 2] = hv.z;
        hs[w][(lane << 2) + 3] = hv.w;
        __syncwarp();
        float acc = bias;
#pragma unroll 16
        for (int j = 0; j < H1; j++)
            acc = fmaf(hs[w][j], W2T[j * QDIM + lane], acc);
        g_q[(size_t)t * QDIM + lane] = acc;
        __syncwarp();
    }
}

// ---------------------------------------------------------------------------
// Kernel 3: scores + top-k + combine + softmax -> (g_wt, g_id)
// Warp per token. Tie-breaking matches lax.top_k (lowest index first).
// ---------------------------------------------------------------------------
__global__ __launch_bounds__(256, 1)
void k3_topk(const float* __restrict__ keys)
{
    __shared__ float ks[2 * 2 * NKEYS * HALFD];   // 32 KB
    __shared__ float sc_s[8][2][2][KNN];
    __shared__ int   id_s[8][2][2][KNN];
    __shared__ float fsc_s[8][2][KNN];
    __shared__ int   fid_s[8][2][KNN];

    const int tid = threadIdx.x;
    for (int i = tid; i < 2 * 2 * NKEYS * HALFD; i += 256) ks[i] = keys[i];
    __syncthreads();

    const int w    = tid >> 5;
    const int lane = tid & 31;
    const int t    = blockIdx.x * 8 + w;
    const float myq = g_q[(size_t)t * QDIM + lane];
    const float NEGINF = __uint_as_float(0xff800000u);

    // 4 units: (head, side)
#pragma unroll
    for (int u = 0; u < 4; u++) {
        const int h = u >> 1, side = u & 1;
        float qv[HALFD];
#pragma unroll
        for (int c = 0; c < HALFD; c++)
            qv[c] = __shfl_sync(0xffffffffu, myq, h * 16 + side * 8 + c);

        float s[8];  // lane owns keys n = i*32 + lane
#pragma unroll
        for (int i = 0; i < 8; i++) {
            const int n = i * 32 + lane;
            const float4 k0 = *(const float4*)&ks[(u * NKEYS + n) * HALFD];
            const float4 k1 = *(const float4*)&ks[(u * NKEYS + n) * HALFD + 4];
            s[i] = qv[0] * k0.x + qv[1] * k0.y + qv[2] * k0.z + qv[3] * k0.w
                 + qv[4] * k1.x + qv[5] * k1.y + qv[6] * k1.z + qv[7] * k1.w;
        }
#pragma unroll
        for (int r = 0; r < KNN; r++) {
            float bv = NEGINF; int bn = 0x7fffffff;
#pragma unroll
            for (int i = 0; i < 8; i++)
                if (s[i] > bv) { bv = s[i]; bn = i * 32 + lane; }
#pragma unroll
            for (int off = 16; off; off >>= 1) {
                const float ov = __shfl_xor_sync(0xffffffffu, bv, off);
                const int   on = __shfl_xor_sync(0xffffffffu, bn, off);
                if (ov > bv || (ov == bv && on < bn)) { bv = ov; bn = on; }
            }
            if (lane == 0) { sc_s[w][h][side][r] = bv; id_s[w][h][side][r] = bn; }
            if ((bn & 31) == lane) s[bn >> 5] = NEGINF;   // kill winner
        }
    }
    __syncwarp();

    // Combine per head: 64 combos = sc1[a] + sc2[b], flat c = a*8 + b
#pragma unroll
    for (int h = 0; h < 2; h++) {
        float v0 = sc_s[w][h][0][lane >> 3]       + sc_s[w][h][1][lane & 7];
        float v1 = sc_s[w][h][0][(lane >> 3) + 4] + sc_s[w][h][1][lane & 7];
#pragma unroll
        for (int r = 0; r < KNN; r++) {
            float bv = v0; int bc = lane;
            if (v1 > bv) { bv = v1; bc = lane + 32; }
#pragma unroll
            for (int off = 16; off; off >>= 1) {
                const float ov = __shfl_xor_sync(0xffffffffu, bv, off);
                const int   oc = __shfl_xor_sync(0xffffffffu, bc, off);
                if (ov > bv || (ov == bv && oc < bc)) { bv = ov; bc = oc; }
            }
            if (lane == 0) {
                fsc_s[w][h][r] = bv;
                const int a = bc >> 3, b = bc & 7;
                fid_s[w][h][r] = id_s[w][h][0][a] * NKEYS + id_s[w][h][1][b];
            }
            if (bc == lane)      v0 = NEGINF;
            if (bc == lane + 32) v1 = NEGINF;
        }
    }
    __syncwarp();

    // Softmax over 8 per head; lanes 0..15 each handle one (h,k) output
    if (lane < 16) {
        const int h = lane >> 3, kk = lane & 7;
        float m = NEGINF;
#pragma unroll
        for (int i = 0; i < KNN; i++) m = fmaxf(m, fsc_s[w][h][i]);
        float den = 0.f;
#pragma unroll
        for (int i = 0; i < KNN; i++) den += expf(fsc_s[w][h][i] - m);
        const float wt = expf(fsc_s[w][h][kk] - m) / den;
        g_wt[t * 16 + lane] = wt;
        g_id[t * 16 + lane] = fid_s[w][h][kk];
    }
}

// ---------------------------------------------------------------------------
// Kernel 4: out[t] = sum_{k<16} w_k * values[idx_k]   (HBM-bound gather)
// Block per token, 256 threads, float4 per thread, 16-deep MLP on loads.
// ---------------------------------------------------------------------------
__global__ __launch_bounds__(256, 1)
void k4_gather(const float* __restrict__ values, float* __restrict__ out)
{
    __shared__ float ws[16];
    __shared__ int   is[16];
    const int t = blockIdx.x;
    if (threadIdx.x < 16) {
        ws[threadIdx.x] = g_wt[t * 16 + threadIdx.x];
        is[threadIdx.x] = g_id[t * 16 + threadIdx.x];
    }
    __syncthreads();
    const int col = threadIdx.x << 2;
    float4 acc = make_float4(0.f, 0.f, 0.f, 0.f);
#pragma unroll
    for (int k = 0; k < 16; k++) {
        const float4 v = __ldg((const float4*)(values + (size_t)is[k] * D_IN + col));
        const float wk = ws[k];
        acc.x = fmaf(wk, v.x, acc.x);
        acc.y = fmaf(wk, v.y, acc.y);
        acc.z = fmaf(wk, v.z, acc.z);
        acc.w = fmaf(wk, v.w, acc.w);
    }
    *(float4*)(out + (size_t)t * D_IN + col) = acc;
}

// ---------------------------------------------------------------------------
extern "C" void kernel_launch(void* const* d_in, const int* in_sizes, int n_in,
                              void* d_out, int out_size)
{
    const float* x      = (const float*)d_in[0];
    const float* W1     = (const float*)d_in[1];
    const float* b1     = (const float*)d_in[2];
    const float* W2     = (const float*)d_in[3];
    const float* b2     = (const float*)d_in[4];
    const float* keys   = (const float*)d_in[5];
    const float* values = (const float*)d_in[6];
    float* out = (float*)d_out;

    k1_gemm_relu<<<T_TOK / BM, 128>>>(x, W1, b1);
    k2_q<<<128, 256>>>(W2, b2);
    k3_topk<<<T_TOK / 8, 256>>>(keys);
    k4_gather<<<T_TOK, 256>>>(values, out);
}